// round 1
// baseline (speedup 1.0000x reference)
#include <cuda_runtime.h>
#include <cstdint>

// Problem constants
#define TT   8
#define NN   100000
#define DD   128
#define EE   50000
#define HH0  64
#define HH1  32

// Scratch (allocation-free rule: __device__ globals)
__device__ float g_sim[EE * TT];   // s1 stored [e][t] for coalesced MLP reads
__device__ int   g_is64;

// ---------------------------------------------------------------------------
// Detect whether edge_list arrived as int64 (JAX x64 on) or int32 (x64 off).
// Values are in [0, 100000), so for int64 every odd 32-bit word (high half)
// is zero. For random int32 data the chance all 64 checked words are zero is ~0.
// ---------------------------------------------------------------------------
__global__ void detect_idx_kernel(const int* __restrict__ w) {
    int all0 = 1;
#pragma unroll
    for (int i = 1; i < 128; i += 2) all0 &= (w[i] == 0);
    g_is64 = all0;
}

// Packed f32x2 helpers (Blackwell FFMA2 path — PTX only)
__device__ __forceinline__ unsigned long long mul2(unsigned long long a, unsigned long long b) {
    unsigned long long r;
    asm("mul.rn.f32x2 %0, %1, %2;" : "=l"(r) : "l"(a), "l"(b));
    return r;
}
__device__ __forceinline__ unsigned long long fma2(unsigned long long a, unsigned long long b, unsigned long long c) {
    unsigned long long r;
    asm("fma.rn.f32x2 %0, %1, %2, %3;" : "=l"(r) : "l"(a), "l"(b), "l"(c));
    return r;
}
__device__ __forceinline__ float hsum2(unsigned long long v) {
    float a, b;
    asm("mov.b64 {%0, %1}, %2;" : "=f"(a), "=f"(b) : "l"(v));
    return a + b;
}

// ---------------------------------------------------------------------------
// Cosine kernel: one warp per (t, edge) pair, grid-stride over pairs.
// Pair ordering is t-major so the concurrent working set is one t-slice of z1
// (51 MB < L2) -> gather repeats hit L2.
// Lane layout: quarter (lane>>3) = head m (0..3); lane&7 selects a 16-element
// d-chunk. Each lane keeps 3 packed accumulators (dot, |a|^2, |b|^2 for its m).
// ---------------------------------------------------------------------------
__global__ void __launch_bounds__(256) cos_kernel(const void* __restrict__ el,
                                                  const float* __restrict__ z1,
                                                  const float* __restrict__ w1) {
    const int lane = threadIdx.x & 31;
    const int m    = lane >> 3;     // head index 0..3
    const int dg   = lane & 7;      // d-chunk 0..7 (16 floats each)
    const int gw   = (int)((blockIdx.x * blockDim.x + threadIdx.x) >> 5);
    const int nw   = (int)((gridDim.x * blockDim.x) >> 5);
    const int is64 = g_is64;

    // Hoist w^2 for this lane's (m, d-chunk): 8 packed f32x2 values
    unsigned long long w2p[8];
    {
        const ulonglong2* wp = (const ulonglong2*)(w1 + m * DD + dg * 16);
#pragma unroll
        for (int i = 0; i < 4; i++) {
            ulonglong2 w = __ldg(wp + i);
            w2p[2 * i]     = mul2(w.x, w.x);
            w2p[2 * i + 1] = mul2(w.y, w.y);
        }
    }

    const int TOTAL = TT * EE;
    for (int pair = gw; pair < TOTAL; pair += nw) {
        const int t = pair / EE;          // t-major => L2 locality per t-slice
        const int e = pair - t * EE;

        int src, dst;
        if (is64) {
            longlong2 v = __ldg((const longlong2*)el + e);
            src = (int)v.x; dst = (int)v.y;
        } else {
            int2 v = __ldg((const int2*)el + e);
            src = v.x; dst = v.y;
        }

        const ulonglong2* ap = (const ulonglong2*)(z1 + ((size_t)t * NN + src) * DD + dg * 16);
        const ulonglong2* bq = (const ulonglong2*)(z1 + ((size_t)t * NN + dst) * DD + dg * 16);

        unsigned long long dacc = 0ull, naacc = 0ull, nbacc = 0ull;
#pragma unroll
        for (int i = 0; i < 4; i++) {
            ulonglong2 a = __ldg(ap + i);
            ulonglong2 b = __ldg(bq + i);
            dacc  = fma2(mul2(a.x, b.x), w2p[2 * i], dacc);
            naacc = fma2(mul2(a.x, a.x), w2p[2 * i], naacc);
            nbacc = fma2(mul2(b.x, b.x), w2p[2 * i], nbacc);
            dacc  = fma2(mul2(a.y, b.y), w2p[2 * i + 1], dacc);
            naacc = fma2(mul2(a.y, a.y), w2p[2 * i + 1], naacc);
            nbacc = fma2(mul2(b.y, b.y), w2p[2 * i + 1], nbacc);
        }

        float dot = hsum2(dacc);
        float na  = hsum2(naacc);
        float nb  = hsum2(nbacc);

        // Reduce the 8 lanes of this quarter (xor 1,2,4 stays inside quarter)
#pragma unroll
        for (int ofs = 1; ofs <= 4; ofs <<= 1) {
            dot += __shfl_xor_sync(0xffffffffu, dot, ofs);
            na  += __shfl_xor_sync(0xffffffffu, na,  ofs);
            nb  += __shfl_xor_sync(0xffffffffu, nb,  ofs);
        }

        // max(sqrt(x), 1e-8) == sqrt(max(x, 1e-16)) for x >= 0
        float den = fmaxf(na, 1e-16f) * fmaxf(nb, 1e-16f);
        float c   = dot * rsqrtf(den);

        // Mean over the 4 heads (sum across quarters)
        c += __shfl_xor_sync(0xffffffffu, c, 8);
        c += __shfl_xor_sync(0xffffffffu, c, 16);

        if (lane == 0) g_sim[e * TT + t] = 0.25f * c;
    }
}

// ---------------------------------------------------------------------------
// MLP kernel: one thread per edge. Weights staged in shared memory
// (uniform-address broadcast LDS.128), h0[64] lives in registers.
// ---------------------------------------------------------------------------
__global__ void __launch_bounds__(256) mlp_kernel(const float* __restrict__ W0,
                                                  const float* __restrict__ b0,
                                                  const float* __restrict__ W1,
                                                  const float* __restrict__ b1,
                                                  const float* __restrict__ Wp,
                                                  const float* __restrict__ bp,
                                                  float* __restrict__ out) {
    __shared__ float sW0[HH0 * TT];      // 512
    __shared__ float sb0[HH0];
    __shared__ float sW1[HH1 * HH0];     // 2048
    __shared__ float sb1[HH1];
    __shared__ float sWp[HH1];
    __shared__ float sbp;

    const int tid = threadIdx.x;
    for (int i = tid; i < HH0 * TT; i += 256) sW0[i] = W0[i];
    for (int i = tid; i < HH1 * HH0; i += 256) sW1[i] = W1[i];
    if (tid < HH0) sb0[tid] = b0[tid];
    if (tid < HH1) { sb1[tid] = b1[tid]; sWp[tid] = Wp[tid]; }
    if (tid == 0) sbp = bp[0];
    __syncthreads();

    const int e = blockIdx.x * 256 + tid;
    if (e >= EE) return;

    float s[8];
    *(float4*)(s)     = *(const float4*)(g_sim + e * 8);
    *(float4*)(s + 4) = *(const float4*)(g_sim + e * 8 + 4);

    float h0[HH0];
#pragma unroll
    for (int j = 0; j < HH0; j++) {
        const float4* w = (const float4*)(sW0 + j * TT);
        float4 wa = w[0], wb = w[1];
        float acc = sb0[j];
        acc += s[0] * wa.x + s[1] * wa.y + s[2] * wa.z + s[3] * wa.w;
        acc += s[4] * wb.x + s[5] * wb.y + s[6] * wb.z + s[7] * wb.w;
        h0[j] = fmaxf(acc, 0.0f);
    }

    float pred = sbp;
    for (int k = 0; k < HH1; k++) {
        float acc = sb1[k];
        const float4* w = (const float4*)(sW1 + k * HH0);
#pragma unroll
        for (int j = 0; j < HH0 / 4; j++) {
            float4 ww = w[j];
            acc += h0[4 * j]     * ww.x + h0[4 * j + 1] * ww.y +
                   h0[4 * j + 2] * ww.z + h0[4 * j + 3] * ww.w;
        }
        pred += fmaxf(acc, 0.0f) * sWp[k];
    }
    out[e] = pred;
}

// ---------------------------------------------------------------------------
// Launch: detect dtype -> fused gather/cosine -> tiny MLP. All graph-capturable.
// Input order (metadata): edge_list, z1_trains, z2_trains(unused),
// weight_vec1, weight_vec2(unused), W0, b0, W1, b1, Wp, bp
// ---------------------------------------------------------------------------
extern "C" void kernel_launch(void* const* d_in, const int* in_sizes, int n_in,
                              void* d_out, int out_size) {
    const void*  edge = d_in[0];
    const float* z1   = (const float*)d_in[1];
    const float* w1   = (const float*)d_in[3];
    const float* W0   = (const float*)d_in[5];
    const float* b0   = (const float*)d_in[6];
    const float* W1   = (const float*)d_in[7];
    const float* b1   = (const float*)d_in[8];
    const float* Wp   = (const float*)d_in[9];
    const float* bp   = (const float*)d_in[10];

    detect_idx_kernel<<<1, 1>>>((const int*)edge);
    cos_kernel<<<1184, 256>>>(edge, z1, w1);
    mlp_kernel<<<(EE + 255) / 256, 256>>>(W0, b0, W1, b1, Wp, bp, (float*)d_out);
}

// round 2
// speedup vs baseline: 1.0357x; 1.0357x over previous
#include <cuda_runtime.h>
#include <cstdint>

// Problem constants
#define TT   8
#define NN   100000
#define DD   128
#define EE   50000
#define HH0  64
#define HH1  32

// Scratch (allocation-free rule: __device__ globals)
__device__ float g_sim[EE * TT];   // s1 stored [e][t] for coalesced MLP reads

// Packed f32x2 helpers (Blackwell FFMA2 path — PTX only)
__device__ __forceinline__ unsigned long long mul2(unsigned long long a, unsigned long long b) {
    unsigned long long r;
    asm("mul.rn.f32x2 %0, %1, %2;" : "=l"(r) : "l"(a), "l"(b));
    return r;
}
__device__ __forceinline__ unsigned long long fma2(unsigned long long a, unsigned long long b, unsigned long long c) {
    unsigned long long r;
    asm("fma.rn.f32x2 %0, %1, %2, %3;" : "=l"(r) : "l"(a), "l"(b), "l"(c));
    return r;
}
__device__ __forceinline__ float hsum2(unsigned long long v) {
    float a, b;
    asm("mov.b64 {%0, %1}, %2;" : "=f"(a), "=f"(b) : "l"(v));
    return a + b;
}

// ---------------------------------------------------------------------------
// Cosine kernel, 2 pairs in flight per warp.
// Warp handles edge e at times (tt, tt+4) simultaneously: same src/dst -> one
// edge fetch, 32 gather LDGs issued together (2x memory-level parallelism),
// and the two reduction chains interleave to hide SHFL latency.
// Lane layout: quarter (lane>>3) = head m; lane&7 = 16-float d-chunk.
// Outer loop over tt keeps the concurrent L2 working set at 2 t-slices
// (102 MB < 126 MB L2).
// int64-vs-int32 edge dtype detected inline per warp (values < 100000 => for
// int64 inputs every odd 32-bit word of the first 8 entries is zero).
// ---------------------------------------------------------------------------
__global__ void __launch_bounds__(256) cos_kernel(const void* __restrict__ el,
                                                  const float* __restrict__ z1,
                                                  const float* __restrict__ w1) {
    const int lane = threadIdx.x & 31;
    const int m    = lane >> 3;     // head index 0..3
    const int dg   = lane & 7;      // d-chunk 0..7 (16 floats each)
    const int gw   = (int)((blockIdx.x * blockDim.x + threadIdx.x) >> 5);
    const int nw   = (int)((gridDim.x * blockDim.x) >> 5);

    // Inline dtype detection (uniform across warp; branch is warp-uniform)
    const int* ew = (const int*)el;
    int is64 = 1;
#pragma unroll
    for (int i = 1; i < 16; i += 2) is64 &= (ew[i] == 0);

    // Hoist w^2 for this lane's (m, d-chunk): 8 packed f32x2 values
    unsigned long long w2p[8];
    {
        const ulonglong2* wp = (const ulonglong2*)(w1 + m * DD + dg * 16);
#pragma unroll
        for (int i = 0; i < 4; i++) {
            ulonglong2 w = __ldg(wp + i);
            w2p[2 * i]     = mul2(w.x, w.x);
            w2p[2 * i + 1] = mul2(w.y, w.y);
        }
    }

#pragma unroll 1
    for (int tt = 0; tt < 4; tt++) {
        const float* zA = z1 + (size_t)tt * NN * DD;        // slice tt
        const float* zB = z1 + (size_t)(tt + 4) * NN * DD;  // slice tt+4

#pragma unroll 1
        for (int e = gw; e < EE; e += nw) {
            int src, dst;
            if (is64) {
                longlong2 v = __ldg((const longlong2*)el + e);
                src = (int)v.x; dst = (int)v.y;
            } else {
                int2 v = __ldg((const int2*)el + e);
                src = v.x; dst = v.y;
            }

            const unsigned os = (unsigned)src * DD + (unsigned)dg * 16;
            const unsigned od = (unsigned)dst * DD + (unsigned)dg * 16;
            const ulonglong2* a0p = (const ulonglong2*)(zA + os);
            const ulonglong2* b0p = (const ulonglong2*)(zA + od);
            const ulonglong2* a1p = (const ulonglong2*)(zB + os);
            const ulonglong2* b1p = (const ulonglong2*)(zB + od);

            // Issue all 32 gather loads (2 pairs) before consuming any
            ulonglong2 A0[4], B0[4], A1[4], B1[4];
#pragma unroll
            for (int i = 0; i < 4; i++) {
                A0[i] = __ldg(a0p + i);
                B0[i] = __ldg(b0p + i);
                A1[i] = __ldg(a1p + i);
                B1[i] = __ldg(b1p + i);
            }

            unsigned long long d0 = 0ull, na0 = 0ull, nb0 = 0ull;
            unsigned long long d1 = 0ull, na1 = 0ull, nb1 = 0ull;
#pragma unroll
            for (int i = 0; i < 4; i++) {
                d0  = fma2(mul2(A0[i].x, B0[i].x), w2p[2 * i], d0);
                na0 = fma2(mul2(A0[i].x, A0[i].x), w2p[2 * i], na0);
                nb0 = fma2(mul2(B0[i].x, B0[i].x), w2p[2 * i], nb0);
                d0  = fma2(mul2(A0[i].y, B0[i].y), w2p[2 * i + 1], d0);
                na0 = fma2(mul2(A0[i].y, A0[i].y), w2p[2 * i + 1], na0);
                nb0 = fma2(mul2(B0[i].y, B0[i].y), w2p[2 * i + 1], nb0);

                d1  = fma2(mul2(A1[i].x, B1[i].x), w2p[2 * i], d1);
                na1 = fma2(mul2(A1[i].x, A1[i].x), w2p[2 * i], na1);
                nb1 = fma2(mul2(B1[i].x, B1[i].x), w2p[2 * i], nb1);
                d1  = fma2(mul2(A1[i].y, B1[i].y), w2p[2 * i + 1], d1);
                na1 = fma2(mul2(A1[i].y, A1[i].y), w2p[2 * i + 1], na1);
                nb1 = fma2(mul2(B1[i].y, B1[i].y), w2p[2 * i + 1], nb1);
            }

            float dot0 = hsum2(d0), sa0 = hsum2(na0), sb0 = hsum2(nb0);
            float dot1 = hsum2(d1), sa1 = hsum2(na1), sb1 = hsum2(nb1);

            // Interleaved quarter reductions (xor 1,2,4 stays inside quarter);
            // the two pairs' chains overlap each other's SHFL latency.
#pragma unroll
            for (int ofs = 1; ofs <= 4; ofs <<= 1) {
                dot0 += __shfl_xor_sync(0xffffffffu, dot0, ofs);
                dot1 += __shfl_xor_sync(0xffffffffu, dot1, ofs);
                sa0  += __shfl_xor_sync(0xffffffffu, sa0,  ofs);
                sa1  += __shfl_xor_sync(0xffffffffu, sa1,  ofs);
                sb0  += __shfl_xor_sync(0xffffffffu, sb0,  ofs);
                sb1  += __shfl_xor_sync(0xffffffffu, sb1,  ofs);
            }

            // max(sqrt(x), 1e-8) == sqrt(max(x, 1e-16)) for x >= 0
            float c0 = dot0 * rsqrtf(fmaxf(sa0, 1e-16f) * fmaxf(sb0, 1e-16f));
            float c1 = dot1 * rsqrtf(fmaxf(sa1, 1e-16f) * fmaxf(sb1, 1e-16f));

            // Mean over 4 heads (sum across quarters)
            c0 += __shfl_xor_sync(0xffffffffu, c0, 8);
            c1 += __shfl_xor_sync(0xffffffffu, c1, 8);
            c0 += __shfl_xor_sync(0xffffffffu, c0, 16);
            c1 += __shfl_xor_sync(0xffffffffu, c1, 16);

            if (lane == 0) {
                g_sim[e * TT + tt]     = 0.25f * c0;
                g_sim[e * TT + tt + 4] = 0.25f * c1;
            }
        }
    }
}

// ---------------------------------------------------------------------------
// MLP kernel: one thread per edge. Weights staged in shared memory
// (uniform-address broadcast LDS.128), h0[64] lives in registers.
// ---------------------------------------------------------------------------
__global__ void __launch_bounds__(256) mlp_kernel(const float* __restrict__ W0,
                                                  const float* __restrict__ b0,
                                                  const float* __restrict__ W1,
                                                  const float* __restrict__ b1,
                                                  const float* __restrict__ Wp,
                                                  const float* __restrict__ bp,
                                                  float* __restrict__ out) {
    __shared__ float sW0[HH0 * TT];      // 512
    __shared__ float sb0[HH0];
    __shared__ float sW1[HH1 * HH0];     // 2048
    __shared__ float sb1[HH1];
    __shared__ float sWp[HH1];
    __shared__ float sbp;

    const int tid = threadIdx.x;
    for (int i = tid; i < HH0 * TT; i += 256) sW0[i] = W0[i];
    for (int i = tid; i < HH1 * HH0; i += 256) sW1[i] = W1[i];
    if (tid < HH0) sb0[tid] = b0[tid];
    if (tid < HH1) { sb1[tid] = b1[tid]; sWp[tid] = Wp[tid]; }
    if (tid == 0) sbp = bp[0];
    __syncthreads();

    const int e = blockIdx.x * 256 + tid;
    if (e >= EE) return;

    float s[8];
    *(float4*)(s)     = *(const float4*)(g_sim + e * 8);
    *(float4*)(s + 4) = *(const float4*)(g_sim + e * 8 + 4);

    float h0[HH0];
#pragma unroll
    for (int j = 0; j < HH0; j++) {
        const float4* w = (const float4*)(sW0 + j * TT);
        float4 wa = w[0], wb = w[1];
        float acc = sb0[j];
        acc += s[0] * wa.x + s[1] * wa.y + s[2] * wa.z + s[3] * wa.w;
        acc += s[4] * wb.x + s[5] * wb.y + s[6] * wb.z + s[7] * wb.w;
        h0[j] = fmaxf(acc, 0.0f);
    }

    float pred = sbp;
    for (int k = 0; k < HH1; k++) {
        float acc = sb1[k];
        const float4* w = (const float4*)(sW1 + k * HH0);
#pragma unroll
        for (int j = 0; j < HH0 / 4; j++) {
            float4 ww = w[j];
            acc += h0[4 * j]     * ww.x + h0[4 * j + 1] * ww.y +
                   h0[4 * j + 2] * ww.z + h0[4 * j + 3] * ww.w;
        }
        pred += fmaxf(acc, 0.0f) * sWp[k];
    }
    out[e] = pred;
}

// ---------------------------------------------------------------------------
// Launch: fused gather/cosine (dtype detection inline) -> tiny MLP.
// Input order (metadata): edge_list, z1_trains, z2_trains(unused),
// weight_vec1, weight_vec2(unused), W0, b0, W1, b1, Wp, bp
// ---------------------------------------------------------------------------
extern "C" void kernel_launch(void* const* d_in, const int* in_sizes, int n_in,
                              void* d_out, int out_size) {
    const void*  edge = d_in[0];
    const float* z1   = (const float*)d_in[1];
    const float* w1   = (const float*)d_in[3];
    const float* W0   = (const float*)d_in[5];
    const float* b0   = (const float*)d_in[6];
    const float* W1   = (const float*)d_in[7];
    const float* b1   = (const float*)d_in[8];
    const float* Wp   = (const float*)d_in[9];
    const float* bp   = (const float*)d_in[10];

    cos_kernel<<<1184, 256>>>(edge, z1, w1);
    mlp_kernel<<<(EE + 255) / 256, 256>>>(W0, b0, W1, b1, Wp, bp, (float*)d_out);
}

// round 3
// speedup vs baseline: 1.0368x; 1.0010x over previous
#include <cuda_runtime.h>
#include <cstdint>

// Problem constants
#define TT   8
#define NN   100000
#define DD   128
#define EE   50000
#define HH0  64
#define HH1  32

// Scratch (allocation-free rule: __device__ globals)
__device__ float g_sim[EE * TT];   // s1 stored [e][t] for coalesced MLP reads

// Packed f32x2 helpers (Blackwell FFMA2 path — PTX only)
__device__ __forceinline__ unsigned long long mul2(unsigned long long a, unsigned long long b) {
    unsigned long long r;
    asm("mul.rn.f32x2 %0, %1, %2;" : "=l"(r) : "l"(a), "l"(b));
    return r;
}
__device__ __forceinline__ unsigned long long fma2(unsigned long long a, unsigned long long b, unsigned long long c) {
    unsigned long long r;
    asm("fma.rn.f32x2 %0, %1, %2, %3;" : "=l"(r) : "l"(a), "l"(b), "l"(c));
    return r;
}
__device__ __forceinline__ float hsum2(unsigned long long v) {
    float a, b;
    asm("mov.b64 {%0, %1}, %2;" : "=f"(a), "=f"(b) : "l"(v));
    return a + b;
}

// ---------------------------------------------------------------------------
// Cosine kernel, 2 pairs in flight per warp.
// Warp handles edge e at times (tt, tt+4) simultaneously: same src/dst -> one
// edge fetch, 32 gather LDGs issued together (2x memory-level parallelism),
// and the two reduction chains interleave to hide SHFL latency.
// Lane layout: quarter (lane>>3) = head m; lane&7 = 16-float d-chunk.
// Outer loop over tt keeps the concurrent L2 working set at 2 t-slices
// (102 MB < 126 MB L2).
// int64-vs-int32 edge dtype detected inline per warp (values < 100000 => for
// int64 inputs every odd 32-bit word of the first 8 entries is zero).
// ---------------------------------------------------------------------------
__global__ void __launch_bounds__(256) cos_kernel(const void* __restrict__ el,
                                                  const float* __restrict__ z1,
                                                  const float* __restrict__ w1) {
    const int lane = threadIdx.x & 31;
    const int m    = lane >> 3;     // head index 0..3
    const int dg   = lane & 7;      // d-chunk 0..7 (16 floats each)
    const int gw   = (int)((blockIdx.x * blockDim.x + threadIdx.x) >> 5);
    const int nw   = (int)((gridDim.x * blockDim.x) >> 5);

    // Inline dtype detection (uniform across warp; branch is warp-uniform)
    const int* ew = (const int*)el;
    int is64 = 1;
#pragma unroll
    for (int i = 1; i < 16; i += 2) is64 &= (ew[i] == 0);

    // Hoist w^2 for this lane's (m, d-chunk): 8 packed f32x2 values
    unsigned long long w2p[8];
    {
        const ulonglong2* wp = (const ulonglong2*)(w1 + m * DD + dg * 16);
#pragma unroll
        for (int i = 0; i < 4; i++) {
            ulonglong2 w = __ldg(wp + i);
            w2p[2 * i]     = mul2(w.x, w.x);
            w2p[2 * i + 1] = mul2(w.y, w.y);
        }
    }

#pragma unroll 1
    for (int tt = 0; tt < 4; tt++) {
        const float* zA = z1 + (size_t)tt * NN * DD;        // slice tt
        const float* zB = z1 + (size_t)(tt + 4) * NN * DD;  // slice tt+4

#pragma unroll 1
        for (int e = gw; e < EE; e += nw) {
            int src, dst;
            if (is64) {
                longlong2 v = __ldg((const longlong2*)el + e);
                src = (int)v.x; dst = (int)v.y;
            } else {
                int2 v = __ldg((const int2*)el + e);
                src = v.x; dst = v.y;
            }

            const unsigned os = (unsigned)src * DD + (unsigned)dg * 16;
            const unsigned od = (unsigned)dst * DD + (unsigned)dg * 16;
            const ulonglong2* a0p = (const ulonglong2*)(zA + os);
            const ulonglong2* b0p = (const ulonglong2*)(zA + od);
            const ulonglong2* a1p = (const ulonglong2*)(zB + os);
            const ulonglong2* b1p = (const ulonglong2*)(zB + od);

            // Issue all 32 gather loads (2 pairs) before consuming any
            ulonglong2 A0[4], B0[4], A1[4], B1[4];
#pragma unroll
            for (int i = 0; i < 4; i++) {
                A0[i] = __ldg(a0p + i);
                B0[i] = __ldg(b0p + i);
                A1[i] = __ldg(a1p + i);
                B1[i] = __ldg(b1p + i);
            }

            unsigned long long d0 = 0ull, na0 = 0ull, nb0 = 0ull;
            unsigned long long d1 = 0ull, na1 = 0ull, nb1 = 0ull;
#pragma unroll
            for (int i = 0; i < 4; i++) {
                d0  = fma2(mul2(A0[i].x, B0[i].x), w2p[2 * i], d0);
                na0 = fma2(mul2(A0[i].x, A0[i].x), w2p[2 * i], na0);
                nb0 = fma2(mul2(B0[i].x, B0[i].x), w2p[2 * i], nb0);
                d0  = fma2(mul2(A0[i].y, B0[i].y), w2p[2 * i + 1], d0);
                na0 = fma2(mul2(A0[i].y, A0[i].y), w2p[2 * i + 1], na0);
                nb0 = fma2(mul2(B0[i].y, B0[i].y), w2p[2 * i + 1], nb0);

                d1  = fma2(mul2(A1[i].x, B1[i].x), w2p[2 * i], d1);
                na1 = fma2(mul2(A1[i].x, A1[i].x), w2p[2 * i], na1);
                nb1 = fma2(mul2(B1[i].x, B1[i].x), w2p[2 * i], nb1);
                d1  = fma2(mul2(A1[i].y, B1[i].y), w2p[2 * i + 1], d1);
                na1 = fma2(mul2(A1[i].y, A1[i].y), w2p[2 * i + 1], na1);
                nb1 = fma2(mul2(B1[i].y, B1[i].y), w2p[2 * i + 1], nb1);
            }

            float dot0 = hsum2(d0), sa0 = hsum2(na0), sb0 = hsum2(nb0);
            float dot1 = hsum2(d1), sa1 = hsum2(na1), sb1 = hsum2(nb1);

            // Interleaved quarter reductions (xor 1,2,4 stays inside quarter);
            // the two pairs' chains overlap each other's SHFL latency.
#pragma unroll
            for (int ofs = 1; ofs <= 4; ofs <<= 1) {
                dot0 += __shfl_xor_sync(0xffffffffu, dot0, ofs);
                dot1 += __shfl_xor_sync(0xffffffffu, dot1, ofs);
                sa0  += __shfl_xor_sync(0xffffffffu, sa0,  ofs);
                sa1  += __shfl_xor_sync(0xffffffffu, sa1,  ofs);
                sb0  += __shfl_xor_sync(0xffffffffu, sb0,  ofs);
                sb1  += __shfl_xor_sync(0xffffffffu, sb1,  ofs);
            }

            // max(sqrt(x), 1e-8) == sqrt(max(x, 1e-16)) for x >= 0
            float c0 = dot0 * rsqrtf(fmaxf(sa0, 1e-16f) * fmaxf(sb0, 1e-16f));
            float c1 = dot1 * rsqrtf(fmaxf(sa1, 1e-16f) * fmaxf(sb1, 1e-16f));

            // Mean over 4 heads (sum across quarters)
            c0 += __shfl_xor_sync(0xffffffffu, c0, 8);
            c1 += __shfl_xor_sync(0xffffffffu, c1, 8);
            c0 += __shfl_xor_sync(0xffffffffu, c0, 16);
            c1 += __shfl_xor_sync(0xffffffffu, c1, 16);

            if (lane == 0) {
                g_sim[e * TT + tt]     = 0.25f * c0;
                g_sim[e * TT + tt + 4] = 0.25f * c1;
            }
        }
    }
}

// ---------------------------------------------------------------------------
// MLP kernel: one thread per edge. Weights staged in shared memory
// (uniform-address broadcast LDS.128), h0[64] lives in registers.
// ---------------------------------------------------------------------------
__global__ void __launch_bounds__(256) mlp_kernel(const float* __restrict__ W0,
                                                  const float* __restrict__ b0,
                                                  const float* __restrict__ W1,
                                                  const float* __restrict__ b1,
                                                  const float* __restrict__ Wp,
                                                  const float* __restrict__ bp,
                                                  float* __restrict__ out) {
    __shared__ float sW0[HH0 * TT];      // 512
    __shared__ float sb0[HH0];
    __shared__ float sW1[HH1 * HH0];     // 2048
    __shared__ float sb1[HH1];
    __shared__ float sWp[HH1];
    __shared__ float sbp;

    const int tid = threadIdx.x;
    for (int i = tid; i < HH0 * TT; i += 256) sW0[i] = W0[i];
    for (int i = tid; i < HH1 * HH0; i += 256) sW1[i] = W1[i];
    if (tid < HH0) sb0[tid] = b0[tid];
    if (tid < HH1) { sb1[tid] = b1[tid]; sWp[tid] = Wp[tid]; }
    if (tid == 0) sbp = bp[0];
    __syncthreads();

    const int e = blockIdx.x * 256 + tid;
    if (e >= EE) return;

    float s[8];
    *(float4*)(s)     = *(const float4*)(g_sim + e * 8);
    *(float4*)(s + 4) = *(const float4*)(g_sim + e * 8 + 4);

    float h0[HH0];
#pragma unroll
    for (int j = 0; j < HH0; j++) {
        const float4* w = (const float4*)(sW0 + j * TT);
        float4 wa = w[0], wb = w[1];
        float acc = sb0[j];
        acc += s[0] * wa.x + s[1] * wa.y + s[2] * wa.z + s[3] * wa.w;
        acc += s[4] * wb.x + s[5] * wb.y + s[6] * wb.z + s[7] * wb.w;
        h0[j] = fmaxf(acc, 0.0f);
    }

    float pred = sbp;
    for (int k = 0; k < HH1; k++) {
        float acc = sb1[k];
        const float4* w = (const float4*)(sW1 + k * HH0);
#pragma unroll
        for (int j = 0; j < HH0 / 4; j++) {
            float4 ww = w[j];
            acc += h0[4 * j]     * ww.x + h0[4 * j + 1] * ww.y +
                   h0[4 * j + 2] * ww.z + h0[4 * j + 3] * ww.w;
        }
        pred += fmaxf(acc, 0.0f) * sWp[k];
    }
    out[e] = pred;
}

// ---------------------------------------------------------------------------
// Launch: fused gather/cosine (dtype detection inline) -> tiny MLP.
// Input order (metadata): edge_list, z1_trains, z2_trains(unused),
// weight_vec1, weight_vec2(unused), W0, b0, W1, b1, Wp, bp
// ---------------------------------------------------------------------------
extern "C" void kernel_launch(void* const* d_in, const int* in_sizes, int n_in,
                              void* d_out, int out_size) {
    const void*  edge = d_in[0];
    const float* z1   = (const float*)d_in[1];
    const float* w1   = (const float*)d_in[3];
    const float* W0   = (const float*)d_in[5];
    const float* b0   = (const float*)d_in[6];
    const float* W1   = (const float*)d_in[7];
    const float* b1   = (const float*)d_in[8];
    const float* Wp   = (const float*)d_in[9];
    const float* bp   = (const float*)d_in[10];

    cos_kernel<<<1184, 256>>>(edge, z1, w1);
    mlp_kernel<<<(EE + 255) / 256, 256>>>(W0, b0, W1, b1, Wp, bp, (float*)d_out);
}